// round 4
// baseline (speedup 1.0000x reference)
#include <cuda_runtime.h>

#define NPTS   32768
#define GRIDSZ 16
#define CDIM   64
#define NVERT  (4 * GRIDSZ * GRIDSZ * GRIDSZ)   // 16384
#define CAP    256

__device__ int  g_cnt[NVERT];
__device__ int2 g_list[NVERT * CAP];            // (point_id, weight bits)

// fused: zero vertex counters + zero output buffer (saves one launch)
__global__ void zero_kernel(float4* __restrict__ out4, int nOut4) {
    int i = blockIdx.x * blockDim.x + threadIdx.x;
    if (i < NVERT) g_cnt[i] = 0;
    if (i < nOut4) out4[i] = make_float4(0.f, 0.f, 0.f, 0.f);
}

__global__ void bin_points_kernel(const int* __restrict__ pidx,
                                  const float* __restrict__ pos)
{
    int p = blockIdx.x * blockDim.x + threadIdx.x;
    if (p >= NPTS) return;

    const int k  = pidx[p];
    const float px = pos[p * 3 + 0] * GRIDSZ - 0.5f;
    const float py = pos[p * 3 + 1] * GRIDSZ - 0.5f;
    const float pz = pos[p * 3 + 2] * GRIDSZ - 0.5f;
    const float fx = floorf(px), fy = floorf(py), fz = floorf(pz);

    float wx[2], wy[2], wz[2];
    wx[1] = px - fx; wx[0] = 1.0f - wx[1];
    wy[1] = py - fy; wy[0] = 1.0f - wy[1];
    wz[1] = pz - fz; wz[0] = 1.0f - wz[1];

    int ix[2], iy[2], iz[2];
    ix[0] = min(max((int)fx,     0), GRIDSZ - 1);
    ix[1] = min(max((int)fx + 1, 0), GRIDSZ - 1);
    iy[0] = min(max((int)fy,     0), GRIDSZ - 1);
    iy[1] = min(max((int)fy + 1, 0), GRIDSZ - 1);
    iz[0] = min(max((int)fz,     0), GRIDSZ - 1);
    iz[1] = min(max((int)fz + 1, 0), GRIDSZ - 1);

    #pragma unroll
    for (int cz = 0; cz < 2; ++cz)
        #pragma unroll
        for (int cy = 0; cy < 2; ++cy)
            #pragma unroll
            for (int cx = 0; cx < 2; ++cx) {
                const float w = wz[cz] * wy[cy] * wx[cx];
                const int v = ((k * GRIDSZ + iz[cz]) * GRIDSZ + iy[cy]) * GRIDSZ + ix[cx];
                int slot = atomicAdd(&g_cnt[v], 1);
                if (slot < CAP)
                    g_list[v * CAP + slot] = make_int2(p, __float_as_int(w));
            }
}

#define GTPB 128

__device__ __forceinline__ void red_add_v4(float* o, float4 v) {
    asm volatile("red.global.add.v4.f32 [%0], {%1,%2,%3,%4};"
                 :: "l"(o), "f"(v.x), "f"(v.y), "f"(v.z), "f"(v.w) : "memory");
}

__device__ __forceinline__ unsigned long long pack2(float v) {
    unsigned long long r;
    asm("mov.b64 %0, {%1, %1};" : "=l"(r) : "f"(v));
    return r;
}

__device__ __forceinline__ float2 unpack2(unsigned long long v) {
    float2 r;
    asm("mov.b64 {%0, %1}, %2;" : "=f"(r.x), "=f"(r.y) : "l"(v));
    return r;
}

// d (packed f32x2) += a * b, full fp32 precision, 1 instruction = 2 FMAs
__device__ __forceinline__ void fma2(unsigned long long& d,
                                     unsigned long long a,
                                     unsigned long long b) {
    asm("fma.rn.f32x2 %0, %1, %2, %0;" : "+l"(d) : "l"(a), "l"(b));
}

__global__ void __launch_bounds__(GTPB) gather_kernel(
    const float* __restrict__ K,     // [NVERT][64][64]
    const float* __restrict__ B,     // [NVERT][64]
    const float* __restrict__ xs,    // [N][64]
    float*       __restrict__ out)   // [N][64]
{
    __shared__ float4             sM[CDIM * 16];   // [c*16+q] = K[c][4q..4q+3]
    __shared__ unsigned long long sXd[16][CDIM];   // duplicated pairs {x,x}
    __shared__ int                sPid[16];
    __shared__ float              sW[16];

    const int v = blockIdx.x;
    int cnt = g_cnt[v];
    if (cnt > CAP) cnt = CAP;
    if (cnt == 0) return;

    const int tid = threadIdx.x;
    const int q = tid & 15;      // channel quad (4 output channels)
    const int g = tid >> 4;      // point slot 0..7 (slots g and g+8)

    const float4* Kf4 = reinterpret_cast<const float4*>(K + (size_t)v * CDIM * CDIM);
    #pragma unroll
    for (int i = 0; i < 8; ++i) sM[tid + i * GTPB] = Kf4[tid + i * GTPB];

    const float4 bq = reinterpret_cast<const float4*>(B + (size_t)v * CDIM)[q];
    const longlong2* sM2 = reinterpret_cast<const longlong2*>(sM);

    for (int base = 0; base < cnt; base += 16) {
        __syncthreads();

        if (tid < 16) {
            const int s = base + tid;
            int pid = 0; float w = 0.0f;
            if (s < cnt) {
                const int2 e = g_list[v * CAP + s];
                pid = e.x; w = __int_as_float(e.y);
            }
            sPid[tid] = pid; sW[tid] = w;
        }
        __syncthreads();

        const bool two = (base + 8 < cnt);   // block-uniform

        {
            const float4 xv0 =
                reinterpret_cast<const float4*>(xs + (size_t)sPid[g] * CDIM)[q];
            ulonglong2* d0 = reinterpret_cast<ulonglong2*>(&sXd[g][4 * q]);
            d0[0] = make_ulonglong2(pack2(xv0.x), pack2(xv0.y));
            d0[1] = make_ulonglong2(pack2(xv0.z), pack2(xv0.w));
            if (two) {
                const float4 xv1 =
                    reinterpret_cast<const float4*>(xs + (size_t)sPid[g + 8] * CDIM)[q];
                ulonglong2* d1 = reinterpret_cast<ulonglong2*>(&sXd[g + 8][4 * q]);
                d1[0] = make_ulonglong2(pack2(xv1.x), pack2(xv1.y));
                d1[1] = make_ulonglong2(pack2(xv1.z), pack2(xv1.w));
            }
        }
        __syncthreads();

        unsigned long long a0lo = 0ull, a0hi = 0ull;   // chans (4q,4q+1),(4q+2,4q+3)
        unsigned long long a1lo = 0ull, a1hi = 0ull;

        if (two) {
            #pragma unroll
            for (int c4 = 0; c4 < 16; ++c4) {
                const longlong2 m0 = sM2[(4 * c4 + 0) * 16 + q];
                const longlong2 m1 = sM2[(4 * c4 + 1) * 16 + q];
                const longlong2 m2 = sM2[(4 * c4 + 2) * 16 + q];
                const longlong2 m3 = sM2[(4 * c4 + 3) * 16 + q];
                const ulonglong2* xp0 = reinterpret_cast<const ulonglong2*>(&sXd[g][4 * c4]);
                const ulonglong2* xp1 = reinterpret_cast<const ulonglong2*>(&sXd[g + 8][4 * c4]);
                const ulonglong2 xa = xp0[0], xb = xp0[1];
                const ulonglong2 ya = xp1[0], yb = xp1[1];

                fma2(a0lo, xa.x, (unsigned long long)m0.x); fma2(a0hi, xa.x, (unsigned long long)m0.y);
                fma2(a0lo, xa.y, (unsigned long long)m1.x); fma2(a0hi, xa.y, (unsigned long long)m1.y);
                fma2(a0lo, xb.x, (unsigned long long)m2.x); fma2(a0hi, xb.x, (unsigned long long)m2.y);
                fma2(a0lo, xb.y, (unsigned long long)m3.x); fma2(a0hi, xb.y, (unsigned long long)m3.y);

                fma2(a1lo, ya.x, (unsigned long long)m0.x); fma2(a1hi, ya.x, (unsigned long long)m0.y);
                fma2(a1lo, ya.y, (unsigned long long)m1.x); fma2(a1hi, ya.y, (unsigned long long)m1.y);
                fma2(a1lo, yb.x, (unsigned long long)m2.x); fma2(a1hi, yb.x, (unsigned long long)m2.y);
                fma2(a1lo, yb.y, (unsigned long long)m3.x); fma2(a1hi, yb.y, (unsigned long long)m3.y);
            }
        } else {
            #pragma unroll
            for (int c4 = 0; c4 < 16; ++c4) {
                const longlong2 m0 = sM2[(4 * c4 + 0) * 16 + q];
                const longlong2 m1 = sM2[(4 * c4 + 1) * 16 + q];
                const longlong2 m2 = sM2[(4 * c4 + 2) * 16 + q];
                const longlong2 m3 = sM2[(4 * c4 + 3) * 16 + q];
                const ulonglong2* xp0 = reinterpret_cast<const ulonglong2*>(&sXd[g][4 * c4]);
                const ulonglong2 xa = xp0[0], xb = xp0[1];

                fma2(a0lo, xa.x, (unsigned long long)m0.x); fma2(a0hi, xa.x, (unsigned long long)m0.y);
                fma2(a0lo, xa.y, (unsigned long long)m1.x); fma2(a0hi, xa.y, (unsigned long long)m1.y);
                fma2(a0lo, xb.x, (unsigned long long)m2.x); fma2(a0hi, xb.x, (unsigned long long)m2.y);
                fma2(a0lo, xb.y, (unsigned long long)m3.x); fma2(a0hi, xb.y, (unsigned long long)m3.y);
            }
        }

        if (base + g < cnt) {
            const float w = sW[g];
            const float2 lo = unpack2(a0lo), hi = unpack2(a0hi);
            float* o = out + (size_t)sPid[g] * CDIM + 4 * q;
            red_add_v4(o, make_float4(w * (lo.x + bq.x), w * (lo.y + bq.y),
                                      w * (hi.x + bq.z), w * (hi.y + bq.w)));
        }
        if (two && (base + 8 + g < cnt)) {
            const float w = sW[g + 8];
            const float2 lo = unpack2(a1lo), hi = unpack2(a1hi);
            float* o = out + (size_t)sPid[g + 8] * CDIM + 4 * q;
            red_add_v4(o, make_float4(w * (lo.x + bq.x), w * (lo.y + bq.y),
                                      w * (hi.x + bq.z), w * (hi.y + bq.w)));
        }
    }
}

extern "C" void kernel_launch(void* const* d_in, const int* in_sizes, int n_in,
                              void* d_out, int out_size)
{
    const int*   pidx = (const int*)  d_in[0];
    const float* pos  = (const float*)d_in[1];
    const float* xs   = (const float*)d_in[2];
    const float* K    = (const float*)d_in[3];
    const float* B    = (const float*)d_in[4];
    float*       out  = (float*)d_out;

    const int nOut4 = out_size / 4;                 // out_size elements of f32
    const int zGrid = (nOut4 + 255) / 256;
    zero_kernel<<<zGrid, 256>>>((float4*)d_out, nOut4);
    bin_points_kernel<<<(NPTS + 127) / 128, 128>>>(pidx, pos);
    gather_kernel<<<NVERT, GTPB>>>(K, B, xs, out);
}